// round 9
// baseline (speedup 1.0000x reference)
#include <cuda_runtime.h>
#include <cstdint>

// CentroidLayer: B=131072, P=64, D=256
#define Dk 256
#define Pk 64
#define TQ 128         // queries per block
#define THREADS 512    // 16 warps
#define QW 8           // queries per warp
#define PITCH_C 260    // c_pk pitch (floats): rows 16B-aligned, conflict-free f4 reads
#define QSTRIDE 260    // qreg per-kk stride: 64 qpairs * 4 + 4 pad
#define PITCH_DP 66    // c_dp pitch
#define WSTRIDE 260    // wbuf per-pp stride

// smem (floats): c_pk [64][260]=16640 | qreg [128][260]=33280 | s_act [64]
// overlay after phase B: c_dp [256][66]=16896 at qreg+0, wbuf [32][260]=8320 at qreg+16896
#define SM_CPK   0
#define SM_QREG  16640
#define SM_SACT  (16640 + 33280)
#define SM_TOTAL (16640 + 33280 + 64)

typedef unsigned long long u64;

__device__ __forceinline__ void fma2(u64 &acc, u64 a, u64 b) {
    asm("fma.rn.f32x2 %0, %1, %2, %0;" : "+l"(acc) : "l"(a), "l"(b));
}
__device__ __forceinline__ float2 u2f(u64 v) {
    float2 r;
    asm("mov.b64 {%0,%1}, %2;" : "=f"(r.x), "=f"(r.y) : "l"(v));
    return r;
}
__device__ __forceinline__ float wsum(float v) {
#pragma unroll
    for (int o = 16; o; o >>= 1) v += __shfl_xor_sync(0xffffffffu, v, o);
    return v;
}

__global__ __launch_bounds__(THREADS, 1)
void centroid_kernel(const float* __restrict__ qemb,
                     const float* __restrict__ cemb,
                     const unsigned char* __restrict__ mask,
                     float* __restrict__ ctx_out,
                     float* __restrict__ w_out,
                     float* __restrict__ h_out,
                     int B, int has_w, int has_h)
{
    extern __shared__ float sm[];
    float* c_pk  = sm + SM_CPK;
    float* qreg  = sm + SM_QREG;
    float* s_act = sm + SM_SACT;
    float* c_dp  = qreg;           // overlay (legal after phase-B sync)
    float* wbuf  = qreg + 16896;   // overlay

    const int tid  = threadIdx.x;
    const int lane = tid & 31;
    const int wid  = tid >> 5;

    // ---- stage centroids (k-contiguous) ----
    for (int idx = tid; idx < Pk * Dk; idx += THREADS) {
        int p = idx >> 8, d = idx & 255;
        c_pk[p * PITCH_C + d] = cemb[idx];
    }
    __syncthreads();

    // ---- centroid inverse norms + activity (warp wid: p = wid*4 .. +3) ----
    bool i32mask = (mask[0] != 0 && mask[1] == 0 && mask[2] == 0 && mask[3] == 0);
#pragma unroll
    for (int pi = 0; pi < 4; pi++) {
        int p = wid * 4 + pi;
        const float4* row = (const float4*)(c_pk + p * PITCH_C);
        float4 a = row[lane], b = row[lane + 32];
        float ss = a.x*a.x + a.y*a.y + a.z*a.z + a.w*a.w
                 + b.x*b.x + b.y*b.y + b.z*b.z + b.w*b.w;
        ss = wsum(ss);
        if (lane == 0) {
            bool act = i32mask ? (((const int*)mask)[p] != 0) : (mask[p] != 0);
            float s = 1.0f / fmaxf(sqrtf(ss), 1e-12f);
            s_act[p] = act ? s : -1.0f;   // sign encodes active flag
        }
    }

    const int qbase = blockIdx.x * TQ + wid * QW;
    const int qp0   = wid * 4;   // this warp's first query-pair slot (4 pairs)

    // ---- Phase A: load + L2-normalize 8 queries, write interleaved [kk][qpair][4] ----
    const float2* q2 = (const float2*)qemb;
#pragma unroll
    for (int qi = 0; qi < QW; qi++) {
        int b = qbase + qi;
        if (b < B) {
            float2 v[4];
            float ss = 0.f;
#pragma unroll
            for (int j = 0; j < 4; j++) {
                v[j] = q2[(size_t)b * (Dk / 2) + lane + 32 * j];
                ss += v[j].x * v[j].x + v[j].y * v[j].y;
            }
            ss = wsum(ss);
            float inv = 1.0f / fmaxf(sqrtf(ss), 1e-12f);
            int qp = qp0 + (qi >> 1), slot = qi & 1;
#pragma unroll
            for (int j = 0; j < 4; j++) {
                int kk = lane + 32 * j;   // k-pair index
                *(float2*)(qreg + kk * QSTRIDE + qp * 4 + slot * 2)
                    = make_float2(v[j].x * inv, v[j].y * inv);
            }
        }
    }
    __syncthreads();

    // ---- Phase B: sims. lane owns p=lane & p=lane+32; 8 q/warp; f32x2 over k ----
    u64 acc[QW][2];
#pragma unroll
    for (int qi = 0; qi < QW; qi++) { acc[qi][0] = 0ull; acc[qi][1] = 0ull; }

    const ulonglong2* ctA = (const ulonglong2*)(c_pk + lane * PITCH_C);
    const ulonglong2* ctB = (const ulonglong2*)(c_pk + (lane + 32) * PITCH_C);

#pragma unroll 2
    for (int kk2 = 0; kk2 < Dk / 4; kk2++) {
        ulonglong2 a4 = ctA[kk2];   // k-pairs 2kk2, 2kk2+1 for p=lane
        ulonglong2 b4 = ctB[kk2];   // same for p=lane+32
        const float* q0 = qreg + (2 * kk2) * QSTRIDE + qp0 * 4;
        const float* q1 = q0 + QSTRIDE;
#pragma unroll
        for (int qp = 0; qp < 4; qp++) {
            ulonglong2 qv = *(const ulonglong2*)(q0 + qp * 4);  // 2 queries @ kk even
            fma2(acc[2*qp  ][0], qv.x, a4.x);
            fma2(acc[2*qp  ][1], qv.x, b4.x);
            fma2(acc[2*qp+1][0], qv.y, a4.x);
            fma2(acc[2*qp+1][1], qv.y, b4.x);
            ulonglong2 qw = *(const ulonglong2*)(q1 + qp * 4);  // 2 queries @ kk odd
            fma2(acc[2*qp  ][0], qw.x, a4.y);
            fma2(acc[2*qp  ][1], qw.x, b4.y);
            fma2(acc[2*qp+1][0], qw.y, a4.y);
            fma2(acc[2*qp+1][1], qw.y, b4.y);
        }
    }
    __syncthreads();   // qreg dead: overlay becomes legal

    // ---- build c_dp (p-contiguous) into overlay ----
    for (int idx = tid; idx < Pk * Dk; idx += THREADS) {
        int p = idx >> 8, d = idx & 255;
        c_dp[d * PITCH_DP + p] = c_pk[p * PITCH_C + d];
    }

    // ---- Phase C: mask + softmax + argmax; write wbuf interleaved [pp][qpair][4] ----
    const float sA = s_act[lane], sB = s_act[lane + 32];
#pragma unroll
    for (int qi = 0; qi < QW; qi++) {
        float2 t0 = u2f(acc[qi][0]);
        float2 t1 = u2f(acc[qi][1]);
        float s0 = (sA > 0.f) ? (t0.x + t0.y) * sA : -1e9f;
        float s1 = (sB > 0.f) ? (t1.x + t1.y) * sB : -1e9f;
        float m; int mi;
        if (s1 > s0) { m = s1; mi = lane + 32; } else { m = s0; mi = lane; }
#pragma unroll
        for (int o = 16; o; o >>= 1) {
            float om = __shfl_xor_sync(0xffffffffu, m, o);
            int   oi = __shfl_xor_sync(0xffffffffu, mi, o);
            if (om > m || (om == m && oi < mi)) { m = om; mi = oi; }
        }
        float e0 = __expf(s0 - m), e1 = __expf(s1 - m);
        float inv = 1.0f / wsum(e0 + e1);
        float w0 = e0 * inv, w1 = e1 * inv;

        int qp = qp0 + (qi >> 1), slot = qi & 1;
        wbuf[(lane >> 1) * WSTRIDE + qp * 4 + slot * 2 + (lane & 1)] = w0;
        wbuf[((lane + 32) >> 1) * WSTRIDE + qp * 4 + slot * 2 + (lane & 1)] = w1;

        int b = qbase + qi;
        if (b < B) {
            if (has_w) {
                w_out[(size_t)b * Pk + lane]      = w0;
                w_out[(size_t)b * Pk + lane + 32] = w1;
            }
            if (has_h && lane == 0) h_out[b] = (float)mi;
        }
    }
    __syncthreads();

    // ---- Phase D: context = W @ C; 4 passes x 2 d-chunks; f32x2 over p-pairs ----
#pragma unroll
    for (int pa = 0; pa < 4; pa++) {
        const int d0 = lane + 32 * (2 * pa);
        const int d1 = lane + 32 * (2 * pa + 1);
        u64 cacc[QW][2];
#pragma unroll
        for (int qi = 0; qi < QW; qi++) { cacc[qi][0] = 0ull; cacc[qi][1] = 0ull; }

#pragma unroll 4
        for (int pp = 0; pp < Pk / 2; pp++) {
            u64 cv0 = *(const u64*)(c_dp + d0 * PITCH_DP + 2 * pp);
            u64 cv1 = *(const u64*)(c_dp + d1 * PITCH_DP + 2 * pp);
            const float* wrow = wbuf + pp * WSTRIDE + qp0 * 4;
#pragma unroll
            for (int qp = 0; qp < 4; qp++) {
                ulonglong2 wv = *(const ulonglong2*)(wrow + qp * 4);
                fma2(cacc[2*qp  ][0], wv.x, cv0);
                fma2(cacc[2*qp  ][1], wv.x, cv1);
                fma2(cacc[2*qp+1][0], wv.y, cv0);
                fma2(cacc[2*qp+1][1], wv.y, cv1);
            }
        }
#pragma unroll
        for (int qi = 0; qi < QW; qi++) {
            int b = qbase + qi;
            if (b < B) {
                float2 t0 = u2f(cacc[qi][0]);
                float2 t1 = u2f(cacc[qi][1]);
                ctx_out[(size_t)b * Dk + d0] = t0.x + t0.y;
                ctx_out[(size_t)b * Dk + d1] = t1.x + t1.y;
            }
        }
    }
}

extern "C" void kernel_launch(void* const* d_in, const int* in_sizes, int n_in,
                              void* d_out, int out_size)
{
    const float* q = (const float*)d_in[0];
    const float* c = (const float*)d_in[1];
    const unsigned char* m = (const unsigned char*)d_in[2];

    const int PD = in_sizes[1];        // P*D
    const int Pn = in_sizes[2];        // P
    const int Dn = PD / Pn;            // D
    const int Bn = in_sizes[0] / Dn;   // B

    float* out = (float*)d_out;
    const long long woff = (long long)Bn * Dn;
    const long long hoff = woff + (long long)Bn * Pn;
    const int has_w = ((long long)out_size >= woff + (long long)Bn * Pn) ? 1 : 0;
    const int has_h = ((long long)out_size >= hoff + (long long)Bn) ? 1 : 0;

    const size_t smem = (size_t)SM_TOTAL * sizeof(float);   // 199,936 B
    cudaFuncSetAttribute(centroid_kernel,
                         cudaFuncAttributeMaxDynamicSharedMemorySize, (int)smem);

    const int grid = (Bn + TQ - 1) / TQ;
    centroid_kernel<<<grid, THREADS, smem>>>(q, c, m, out, out + woff, out + hoff,
                                             Bn, has_w, has_h);
}

// round 10
// speedup vs baseline: 1.0086x; 1.0086x over previous
#include <cuda_runtime.h>
#include <cstdint>

// CentroidLayer: B=131072, P=64, D=256
#define Dk 256
#define Pk 64
#define TQ 128         // queries per block
#define THREADS 512    // 16 warps
#define QW 8           // queries per warp
#define PITCH_C 260    // c_pk pitch (floats): rows 16B-aligned, conflict-free f4 reads
#define QSTRIDE 260    // qreg per-kk stride: 64 qpairs * 4 + 4 pad
#define PITCH_DP 66    // c_dp pitch
#define WSTRIDE 260    // wbuf per-pp stride

// smem (floats): c_pk [64][260]=16640 | qreg [128][260]=33280 | s_act [64]
// overlay after phase B: c_dp [256][66]=16896 at qreg+0, wbuf [32][260]=8320 at qreg+16896
#define SM_CPK   0
#define SM_QREG  16640
#define SM_SACT  (16640 + 33280)
#define SM_TOTAL (16640 + 33280 + 64)

typedef unsigned long long u64;

__device__ __forceinline__ void fma2(u64 &acc, u64 a, u64 b) {
    asm("fma.rn.f32x2 %0, %1, %2, %0;" : "+l"(acc) : "l"(a), "l"(b));
}
__device__ __forceinline__ float2 u2f(u64 v) {
    float2 r;
    asm("mov.b64 {%0,%1}, %2;" : "=f"(r.x), "=f"(r.y) : "l"(v));
    return r;
}
__device__ __forceinline__ float wsum(float v) {
#pragma unroll
    for (int o = 16; o; o >>= 1) v += __shfl_xor_sync(0xffffffffu, v, o);
    return v;
}

__global__ __launch_bounds__(THREADS, 1)
void centroid_kernel(const float* __restrict__ qemb,
                     const float* __restrict__ cemb,
                     const unsigned char* __restrict__ mask,
                     float* __restrict__ ctx_out,
                     float* __restrict__ w_out,
                     float* __restrict__ h_out,
                     int B, int has_w, int has_h)
{
    extern __shared__ float sm[];
    float* c_pk  = sm + SM_CPK;
    float* qreg  = sm + SM_QREG;
    float* s_act = sm + SM_SACT;
    float* c_dp  = qreg;           // overlay (legal after phase-B sync)
    float* wbuf  = qreg + 16896;   // overlay

    const int tid  = threadIdx.x;
    const int lane = tid & 31;
    const int wid  = tid >> 5;

    // ---- stage centroids (k-contiguous) ----
    for (int idx = tid; idx < Pk * Dk; idx += THREADS) {
        int p = idx >> 8, d = idx & 255;
        c_pk[p * PITCH_C + d] = cemb[idx];
    }
    __syncthreads();

    // ---- centroid inverse norms + activity (warp wid: p = wid*4 .. +3) ----
    bool i32mask = (mask[0] != 0 && mask[1] == 0 && mask[2] == 0 && mask[3] == 0);
#pragma unroll
    for (int pi = 0; pi < 4; pi++) {
        int p = wid * 4 + pi;
        const float4* row = (const float4*)(c_pk + p * PITCH_C);
        float4 a = row[lane], b = row[lane + 32];
        float ss = a.x*a.x + a.y*a.y + a.z*a.z + a.w*a.w
                 + b.x*b.x + b.y*b.y + b.z*b.z + b.w*b.w;
        ss = wsum(ss);
        if (lane == 0) {
            bool act = i32mask ? (((const int*)mask)[p] != 0) : (mask[p] != 0);
            float s = 1.0f / fmaxf(sqrtf(ss), 1e-12f);
            s_act[p] = act ? s : -1.0f;   // sign encodes active flag
        }
    }

    const int qbase = blockIdx.x * TQ + wid * QW;
    const int qp0   = wid * 4;   // this warp's first query-pair slot (4 pairs)

    // ---- Phase A: load + L2-normalize 8 queries, write interleaved [kk][qpair][4] ----
    const float2* q2 = (const float2*)qemb;
#pragma unroll
    for (int qi = 0; qi < QW; qi++) {
        int b = qbase + qi;
        if (b < B) {
            float2 v[4];
            float ss = 0.f;
#pragma unroll
            for (int j = 0; j < 4; j++) {
                v[j] = q2[(size_t)b * (Dk / 2) + lane + 32 * j];
                ss += v[j].x * v[j].x + v[j].y * v[j].y;
            }
            ss = wsum(ss);
            float inv = 1.0f / fmaxf(sqrtf(ss), 1e-12f);
            int qp = qp0 + (qi >> 1), slot = qi & 1;
#pragma unroll
            for (int j = 0; j < 4; j++) {
                int kk = lane + 32 * j;   // k-pair index
                *(float2*)(qreg + kk * QSTRIDE + qp * 4 + slot * 2)
                    = make_float2(v[j].x * inv, v[j].y * inv);
            }
        }
    }
    __syncthreads();

    // ---- Phase B: sims. lane owns p=lane & p=lane+32; 8 q/warp; f32x2 over k ----
    u64 acc[QW][2];
#pragma unroll
    for (int qi = 0; qi < QW; qi++) { acc[qi][0] = 0ull; acc[qi][1] = 0ull; }

    const ulonglong2* ctA = (const ulonglong2*)(c_pk + lane * PITCH_C);
    const ulonglong2* ctB = (const ulonglong2*)(c_pk + (lane + 32) * PITCH_C);

#pragma unroll 2
    for (int kk2 = 0; kk2 < Dk / 4; kk2++) {
        ulonglong2 a4 = ctA[kk2];   // k-pairs 2kk2, 2kk2+1 for p=lane
        ulonglong2 b4 = ctB[kk2];   // same for p=lane+32
        const float* q0 = qreg + (2 * kk2) * QSTRIDE + qp0 * 4;
        const float* q1 = q0 + QSTRIDE;
#pragma unroll
        for (int qp = 0; qp < 4; qp++) {
            ulonglong2 qv = *(const ulonglong2*)(q0 + qp * 4);  // 2 queries @ kk even
            fma2(acc[2*qp  ][0], qv.x, a4.x);
            fma2(acc[2*qp  ][1], qv.x, b4.x);
            fma2(acc[2*qp+1][0], qv.y, a4.x);
            fma2(acc[2*qp+1][1], qv.y, b4.x);
            ulonglong2 qw = *(const ulonglong2*)(q1 + qp * 4);  // 2 queries @ kk odd
            fma2(acc[2*qp  ][0], qw.x, a4.y);
            fma2(acc[2*qp  ][1], qw.x, b4.y);
            fma2(acc[2*qp+1][0], qw.y, a4.y);
            fma2(acc[2*qp+1][1], qw.y, b4.y);
        }
    }
    __syncthreads();   // qreg dead: overlay becomes legal

    // ---- build c_dp (p-contiguous) into overlay ----
    for (int idx = tid; idx < Pk * Dk; idx += THREADS) {
        int p = idx >> 8, d = idx & 255;
        c_dp[d * PITCH_DP + p] = c_pk[p * PITCH_C + d];
    }

    // ---- Phase C: mask + softmax + argmax; write wbuf interleaved [pp][qpair][4] ----
    const float sA = s_act[lane], sB = s_act[lane + 32];
#pragma unroll
    for (int qi = 0; qi < QW; qi++) {
        float2 t0 = u2f(acc[qi][0]);
        float2 t1 = u2f(acc[qi][1]);
        float s0 = (sA > 0.f) ? (t0.x + t0.y) * sA : -1e9f;
        float s1 = (sB > 0.f) ? (t1.x + t1.y) * sB : -1e9f;
        float m; int mi;
        if (s1 > s0) { m = s1; mi = lane + 32; } else { m = s0; mi = lane; }
#pragma unroll
        for (int o = 16; o; o >>= 1) {
            float om = __shfl_xor_sync(0xffffffffu, m, o);
            int   oi = __shfl_xor_sync(0xffffffffu, mi, o);
            if (om > m || (om == m && oi < mi)) { m = om; mi = oi; }
        }
        float e0 = __expf(s0 - m), e1 = __expf(s1 - m);
        float inv = 1.0f / wsum(e0 + e1);
        float w0 = e0 * inv, w1 = e1 * inv;

        int qp = qp0 + (qi >> 1), slot = qi & 1;
        wbuf[(lane >> 1) * WSTRIDE + qp * 4 + slot * 2 + (lane & 1)] = w0;
        wbuf[((lane + 32) >> 1) * WSTRIDE + qp * 4 + slot * 2 + (lane & 1)] = w1;

        int b = qbase + qi;
        if (b < B) {
            if (has_w) {
                w_out[(size_t)b * Pk + lane]      = w0;
                w_out[(size_t)b * Pk + lane + 32] = w1;
            }
            if (has_h && lane == 0) h_out[b] = (float)mi;
        }
    }
    __syncthreads();

    // ---- Phase D: context = W @ C; 4 passes x 2 d-chunks; f32x2 over p-pairs ----
#pragma unroll
    for (int pa = 0; pa < 4; pa++) {
        const int d0 = lane + 32 * (2 * pa);
        const int d1 = lane + 32 * (2 * pa + 1);
        u64 cacc[QW][2];
#pragma unroll
        for (int qi = 0; qi < QW; qi++) { cacc[qi][0] = 0ull; cacc[qi][1] = 0ull; }

#pragma unroll 4
        for (int pp = 0; pp < Pk / 2; pp++) {
            u64 cv0 = *(const u64*)(c_dp + d0 * PITCH_DP + 2 * pp);
            u64 cv1 = *(const u64*)(c_dp + d1 * PITCH_DP + 2 * pp);
            const float* wrow = wbuf + pp * WSTRIDE + qp0 * 4;
#pragma unroll
            for (int qp = 0; qp < 4; qp++) {
                ulonglong2 wv = *(const ulonglong2*)(wrow + qp * 4);
                fma2(cacc[2*qp  ][0], wv.x, cv0);
                fma2(cacc[2*qp  ][1], wv.x, cv1);
                fma2(cacc[2*qp+1][0], wv.y, cv0);
                fma2(cacc[2*qp+1][1], wv.y, cv1);
            }
        }
#pragma unroll
        for (int qi = 0; qi < QW; qi++) {
            int b = qbase + qi;
            if (b < B) {
                float2 t0 = u2f(cacc[qi][0]);
                float2 t1 = u2f(cacc[qi][1]);
                ctx_out[(size_t)b * Dk + d0] = t0.x + t0.y;
                ctx_out[(size_t)b * Dk + d1] = t1.x + t1.y;
            }
        }
    }
}

extern "C" void kernel_launch(void* const* d_in, const int* in_sizes, int n_in,
                              void* d_out, int out_size)
{
    const float* q = (const float*)d_in[0];
    const float* c = (const float*)d_in[1];
    const unsigned char* m = (const unsigned char*)d_in[2];

    const int PD = in_sizes[1];        // P*D
    const int Pn = in_sizes[2];        // P
    const int Dn = PD / Pn;            // D
    const int Bn = in_sizes[0] / Dn;   // B

    float* out = (float*)d_out;
    const long long woff = (long long)Bn * Dn;
    const long long hoff = woff + (long long)Bn * Pn;
    const int has_w = ((long long)out_size >= woff + (long long)Bn * Pn) ? 1 : 0;
    const int has_h = ((long long)out_size >= hoff + (long long)Bn) ? 1 : 0;

    const size_t smem = (size_t)SM_TOTAL * sizeof(float);   // 199,936 B
    cudaFuncSetAttribute(centroid_kernel,
                         cudaFuncAttributeMaxDynamicSharedMemorySize, (int)smem);

    const int grid = (Bn + TQ - 1) / TQ;
    centroid_kernel<<<grid, THREADS, smem>>>(q, c, m, out, out + woff, out + hoff,
                                             Bn, has_w, has_h);
}